// round 7
// baseline (speedup 1.0000x reference)
#include <cuda_runtime.h>
#include <cstdint>

#define NN 100000
#define NE 1600000
#define D  128
#define SCAN_BLOCKS 98   // ceil(NN / 1024)

// ---------------- scratch (device globals — no allocation allowed) ----------
__device__ __align__(16) int   g_cursor[NN];
__device__ __align__(16) int   g_rowptr[NN + 1];
__device__ __align__(16) int   g_blocksum[SCAN_BLOCKS];
__device__ __align__(16) int   g_col[NE];
__device__ __align__(16) float g_h1 [(size_t)NN * D];
__device__ __align__(16) float g_h2 [(size_t)NN * D];
// pre-transposed tf32-rounded weights: WT[layer][n=128][k=256] = [w_rel;w_root]^T
__device__ __align__(16) float g_wt [3 * 128 * 256];

__device__ __forceinline__ float tf32_rna(float x) {
    float r; asm("cvt.rna.tf32.f32 %0, %1;" : "=f"(r) : "f"(x)); return r;
}

// warp-level tensor-core mma (baseline PTX, works on compute_103)
__device__ __forceinline__ void mma_tf32(float* c, const uint32_t* a,
                                         uint32_t b0, uint32_t b1) {
    asm volatile(
        "mma.sync.aligned.m16n8k8.row.col.f32.tf32.tf32.f32 "
        "{%0,%1,%2,%3}, {%4,%5,%6,%7}, {%8,%9}, {%0,%1,%2,%3};"
        : "+f"(c[0]), "+f"(c[1]), "+f"(c[2]), "+f"(c[3])
        : "r"(a[0]), "r"(a[1]), "r"(a[2]), "r"(a[3]), "r"(b0), "r"(b1));
}

// ---------------- CSR build --------------------------------------------------
__global__ void zero_cursor_kernel() {
    int i = blockIdx.x * blockDim.x + threadIdx.x;
    if (i < NN) g_cursor[i] = 0;
}

__global__ void hist_kernel(const int* __restrict__ ei) {
    int e = blockIdx.x * blockDim.x + threadIdx.x;
    if (e < NE) {
        int dst = ei[NE + e];
        if ((unsigned)dst < NN) atomicAdd(&g_cursor[dst], 1);
    }
}

// ---- 3-pass parallel exclusive scan of g_cursor -> g_rowptr ----
__global__ void scan1_kernel() {
    const int tid  = threadIdx.x;
    const int lane = tid & 31;
    const int warp = tid >> 5;
    const int i    = blockIdx.x * 1024 + tid;
    int v = (i < NN) ? g_cursor[i] : 0;
    int x = v;
    #pragma unroll
    for (int off = 1; off < 32; off <<= 1) {
        int t = __shfl_up_sync(0xFFFFFFFFu, x, off);
        if (lane >= off) x += t;
    }
    __shared__ int wsum[32];
    if (lane == 31) wsum[warp] = x;
    __syncthreads();
    if (warp == 0) {
        int y = wsum[lane];
        #pragma unroll
        for (int off = 1; off < 32; off <<= 1) {
            int t = __shfl_up_sync(0xFFFFFFFFu, y, off);
            if (lane >= off) y += t;
        }
        wsum[lane] = y;
    }
    __syncthreads();
    int blockExcl = (warp > 0) ? wsum[warp - 1] : 0;
    if (i < NN) g_rowptr[i] = blockExcl + x - v;
    if (tid == 1023) g_blocksum[blockIdx.x] = blockExcl + x;
}

__global__ void scan2_kernel() {   // 1 block, 128 threads
    __shared__ int s[128];
    int tid = threadIdx.x;
    int v = (tid < SCAN_BLOCKS) ? g_blocksum[tid] : 0;
    s[tid] = v;
    __syncthreads();
    #pragma unroll
    for (int off = 1; off < 128; off <<= 1) {
        int t = (tid >= off) ? s[tid - off] : 0;
        __syncthreads();
        s[tid] += t;
        __syncthreads();
    }
    if (tid < SCAN_BLOCKS) g_blocksum[tid] = s[tid] - v;
    if (tid == SCAN_BLOCKS - 1) g_rowptr[NN] = s[tid];
}

__global__ void scan3_kernel() {
    int i = blockIdx.x * 1024 + threadIdx.x;
    if (i < NN) g_rowptr[i] += g_blocksum[blockIdx.x];
}

__global__ void fill_kernel(const int* __restrict__ ei) {
    int e = blockIdx.x * blockDim.x + threadIdx.x;
    if (e < NE) {
        int src = ei[e];
        int dst = ei[NE + e];
        if ((unsigned)dst < NN && (unsigned)src < NN) {
            int pos = atomicAdd(&g_cursor[dst], 1);
            g_col[g_rowptr[dst] + pos] = src;
        }
    }
}

// ---------------- weight prep: WT[l][n][k] = tf32(W[l][k][n]) ----------------
__global__ void prep_wt_kernel(const float* __restrict__ wr1, const float* __restrict__ wo1,
                               const float* __restrict__ wr2, const float* __restrict__ wo2,
                               const float* __restrict__ wr3, const float* __restrict__ wo3) {
    int i = blockIdx.x * blockDim.x + threadIdx.x;   // over 3*128*256
    if (i >= 3 * 128 * 256) return;
    int l = i >> 15;
    int r = i & 32767;
    int n = r >> 8;
    int k = r & 255;
    const float* wr = (l == 0) ? wr1 : (l == 1 ? wr2 : wr3);
    const float* wo = (l == 0) ? wo1 : (l == 1 ? wo2 : wo3);
    float v = (k < 128) ? wr[k * 128 + n] : wo[(k - 128) * 128 + n];
    g_wt[i] = tf32_rna(v);
}

// ---------------- fused agg + TF32 mma.sync GEMM ------------------------------
// out = act([segsum(h[src]->dst) | h] @ WT^T + b)
// Phase 0: gather/aggregate the CTA's 128 node rows into SMEM (aggS, padded).
// Phase 1: 128x128 GEMM, K=256 in 8 chunks of 32; chunks 0-3 read aggS,
//          chunks 4-7 read h from global. 8 warps (4M x 2N), 64 acc/thread.
// Dynamic SMEM: aggS 128*132*4 = 67584 B | sA 16384 B | sB 16384 B.
#define AGG_STRIDE 132
#define SMEM_SA_OFF   (128 * AGG_STRIDE)            // in floats
#define SMEM_SB_OFF   (SMEM_SA_OFF + 4096)
#define GEMM_SMEM_B   ((SMEM_SB_OFF + 4096) * 4)    // 100352 bytes

template <bool RELU>
__global__ void __launch_bounds__(256, 2)
gemm_fused_kernel(const float* __restrict__ xin, int which, int layer,
                  const float* __restrict__ bias,
                  float* __restrict__ outarg, int outsel)
{
    extern __shared__ float smemf[];
    float* aggS = smemf;                 // [128][AGG_STRIDE]
    float* sA   = smemf + SMEM_SA_OFF;   // [4096] fragment-major
    float* sB   = smemf + SMEM_SB_OFF;   // [4096] fragment-major

    const float* H   = (which == 0) ? xin : (which == 1 ? g_h1 : g_h2);
    float*       out = (outsel == 0) ? g_h1 : (outsel == 1 ? g_h2 : outarg);
    const float* wt  = &g_wt[layer * 128 * 256];

    const int tid  = threadIdx.x;
    const int lane = tid & 31;
    const int wid  = tid >> 5;
    const int wm   = wid & 3;     // 0..3  -> M
    const int wn   = wid >> 2;    // 0..1  -> N
    const int m0   = blockIdx.x * 128;

    // ---- phase 0: aggregate this tile's 128 nodes into aggS ----
    {
        const float4* hv = (const float4*)H;
        #pragma unroll 1
        for (int t = 0; t < 16; t++) {
            int r    = wid * 16 + t;
            int node = m0 + r;
            float4 acc = make_float4(0.f, 0.f, 0.f, 0.f);
            if (node < NN) {
                int beg = g_rowptr[node];
                int end = g_rowptr[node + 1];
                int j = beg;
                for (; j + 4 <= end; j += 4) {
                    int s0 = g_col[j], s1 = g_col[j + 1];
                    int s2 = g_col[j + 2], s3 = g_col[j + 3];
                    float4 v0 = hv[(size_t)s0 * 32 + lane];
                    float4 v1 = hv[(size_t)s1 * 32 + lane];
                    float4 v2 = hv[(size_t)s2 * 32 + lane];
                    float4 v3 = hv[(size_t)s3 * 32 + lane];
                    acc.x += v0.x + v1.x + v2.x + v3.x;
                    acc.y += v0.y + v1.y + v2.y + v3.y;
                    acc.z += v0.z + v1.z + v2.z + v3.z;
                    acc.w += v0.w + v1.w + v2.w + v3.w;
                }
                for (; j < end; j++) {
                    int s = g_col[j];
                    float4 v = hv[(size_t)s * 32 + lane];
                    acc.x += v.x; acc.y += v.y; acc.z += v.z; acc.w += v.w;
                }
            }
            *(float4*)&aggS[r * AGG_STRIDE + lane * 4] = acc;
        }
    }
    __syncthreads();

    // ---- phase 1: GEMM over K=256 ----
    float acc[2][8][4];
    #pragma unroll
    for (int i = 0; i < 2; i++)
        #pragma unroll
        for (int j = 0; j < 8; j++)
            #pragma unroll
            for (int k = 0; k < 4; k++) acc[i][j][k] = 0.f;

    #pragma unroll 1
    for (int c = 0; c < 8; c++) {
        if (c > 0) __syncthreads();   // protect previous chunk's smem reads

        // ---- stage A chunk (fragment-major, tf32-converted) ----
        {
            const int kbase = (c & 3) * 32;
            #pragma unroll
            for (int it = 0; it < 4; it++) {
                int fidx = it * 256 + tid;
                int r  = fidx >> 3;
                int cq = fidx & 7;
                float4 v;
                if (c < 4) {
                    v = *(const float4*)&aggS[r * AGG_STRIDE + kbase + cq * 4];
                } else {
                    v = make_float4(0.f, 0.f, 0.f, 0.f);
                    if (m0 + r < NN)
                        v = *(const float4*)&H[(size_t)(m0 + r) * 128 + kbase + cq * 4];
                }
                int mt = r >> 4, rr = r & 15, g = rr & 7, jo = rr >> 3;
                int ks = cq >> 1;
                int j  = jo + ((cq & 1) << 1);
                int base = (ks * 8 + mt) * 128 + g * 16 + j;
                sA[base +  0] = tf32_rna(v.x);
                sA[base +  4] = tf32_rna(v.y);
                sA[base +  8] = tf32_rna(v.z);
                sA[base + 12] = tf32_rna(v.w);
            }
        }
        // ---- stage B chunk (fragment-major; wt already tf32) ----
        {
            const int kbase = c * 32;
            #pragma unroll
            for (int it = 0; it < 4; it++) {
                int fidx = it * 256 + tid;
                int n  = fidx >> 3;
                int cq = fidx & 7;
                float4 v = *(const float4*)&wt[(size_t)n * 256 + kbase + cq * 4];
                int nt = n >> 3, g = n & 7;
                int ks = cq >> 1;
                int j  = cq & 1;
                int base = (ks * 16 + nt) * 64 + g * 8 + j;
                sB[base + 0] = v.x;
                sB[base + 2] = v.y;
                sB[base + 4] = v.z;
                sB[base + 6] = v.w;
            }
        }
        __syncthreads();

        // ---- compute: 4 ksteps x (2 M-tiles x 8 N-tiles) mma ----
        #pragma unroll
        for (int ks = 0; ks < 4; ks++) {
            uint32_t a[2][4];
            #pragma unroll
            for (int mtl = 0; mtl < 2; mtl++) {
                int mt = wm * 2 + mtl;
                float4 af = *(const float4*)&sA[((ks * 8 + mt) * 32 + lane) * 4];
                a[mtl][0] = __float_as_uint(af.x);
                a[mtl][1] = __float_as_uint(af.y);
                a[mtl][2] = __float_as_uint(af.z);
                a[mtl][3] = __float_as_uint(af.w);
            }
            #pragma unroll
            for (int ntl = 0; ntl < 8; ntl++) {
                int nt = wn * 8 + ntl;
                float2 bf = *(const float2*)&sB[((ks * 16 + nt) * 32 + lane) * 2];
                uint32_t b0 = __float_as_uint(bf.x);
                uint32_t b1 = __float_as_uint(bf.y);
                mma_tf32(acc[0][ntl], a[0], b0, b1);
                mma_tf32(acc[1][ntl], a[1], b0, b1);
            }
        }
    }

    // ---- epilogue: bias + optional relu, float2 stores ----
    const int g   = lane >> 2;
    const int tig = lane & 3;
    #pragma unroll
    for (int mtl = 0; mtl < 2; mtl++) {
        #pragma unroll
        for (int h = 0; h < 2; h++) {
            int row = m0 + wm * 32 + mtl * 16 + h * 8 + g;
            if (row >= NN) continue;
            #pragma unroll
            for (int ntl = 0; ntl < 8; ntl++) {
                int col = wn * 64 + ntl * 8 + tig * 2;
                float2 o;
                o.x = acc[mtl][ntl][h * 2 + 0] + __ldg(&bias[col + 0]);
                o.y = acc[mtl][ntl][h * 2 + 1] + __ldg(&bias[col + 1]);
                if (RELU) { o.x = fmaxf(o.x, 0.f); o.y = fmaxf(o.y, 0.f); }
                *(float2*)&out[(size_t)row * 128 + col] = o;
            }
        }
    }
}

// ---------------- launch ------------------------------------------------------
extern "C" void kernel_launch(void* const* d_in, const int* in_sizes, int n_in,
                              void* d_out, int out_size) {
    const float* x       = (const float*)d_in[0];
    const int*   ei      = (const int*)d_in[1];
    const float* w_rel1  = (const float*)d_in[2];
    const float* w_root1 = (const float*)d_in[3];
    const float* b1      = (const float*)d_in[4];
    const float* w_rel2  = (const float*)d_in[5];
    const float* w_root2 = (const float*)d_in[6];
    const float* b2      = (const float*)d_in[7];
    const float* w_rel3  = (const float*)d_in[8];
    const float* w_root3 = (const float*)d_in[9];
    const float* b3      = (const float*)d_in[10];
    float*       out     = (float*)d_out;

    cudaFuncSetAttribute(gemm_fused_kernel<true>,
                         cudaFuncAttributeMaxDynamicSharedMemorySize, GEMM_SMEM_B);
    cudaFuncSetAttribute(gemm_fused_kernel<false>,
                         cudaFuncAttributeMaxDynamicSharedMemorySize, GEMM_SMEM_B);

    const int ZB = (NN + 255) / 256;
    const int EB = (NE + 255) / 256;
    const int GB = (NN + 127) / 128;            // 782

    // CSR build + weight prep
    zero_cursor_kernel<<<ZB, 256>>>();
    hist_kernel<<<EB, 256>>>(ei);
    prep_wt_kernel<<<384, 256>>>(w_rel1, w_root1, w_rel2, w_root2, w_rel3, w_root3);
    scan1_kernel<<<SCAN_BLOCKS, 1024>>>();
    scan2_kernel<<<1, 128>>>();
    scan3_kernel<<<SCAN_BLOCKS, 1024>>>();
    zero_cursor_kernel<<<ZB, 256>>>();
    fill_kernel<<<EB, 256>>>(ei);

    // fused layers
    gemm_fused_kernel<true ><<<GB, 256, GEMM_SMEM_B>>>(x, 0, 0, b1, nullptr, 0);
    gemm_fused_kernel<true ><<<GB, 256, GEMM_SMEM_B>>>(x, 1, 1, b2, nullptr, 1);
    gemm_fused_kernel<false><<<GB, 256, GEMM_SMEM_B>>>(x, 2, 2, b3, out, 2);
}

// round 8
// speedup vs baseline: 1.4392x; 1.4392x over previous
#include <cuda_runtime.h>
#include <cuda_fp16.h>
#include <cstdint>

#define NN 100000
#define NE 1600000
#define D  128
#define SCAN_BLOCKS 98   // ceil(NN / 1024)

// ---------------- scratch (device globals — no allocation allowed) ----------
__device__ __align__(16) int    g_cursor[NN];
__device__ __align__(16) int    g_rowptr[NN + 1];
__device__ __align__(16) int    g_blocksum[SCAN_BLOCKS];
__device__ __align__(16) int    g_col[NE];
__device__ __align__(16) float  g_agg[(size_t)NN * D];
__device__ __align__(16) float  g_h1 [(size_t)NN * D];
__device__ __align__(16) float  g_h2 [(size_t)NN * D];
__device__ __align__(16) __half g_hh [(size_t)NN * D];   // fp16 gather copy
// pre-transposed tf32-rounded weights: WT[layer][n=128][k=256] = [w_rel;w_root]^T
__device__ __align__(16) float  g_wt [3 * 128 * 256];

__device__ __forceinline__ float tf32_rna(float x) {
    float r; asm("cvt.rna.tf32.f32 %0, %1;" : "=f"(r) : "f"(x)); return r;
}

// warp-level tensor-core mma (baseline PTX, works on compute_103)
__device__ __forceinline__ void mma_tf32(float* c, const uint32_t* a,
                                         uint32_t b0, uint32_t b1) {
    asm volatile(
        "mma.sync.aligned.m16n8k8.row.col.f32.tf32.tf32.f32 "
        "{%0,%1,%2,%3}, {%4,%5,%6,%7}, {%8,%9}, {%0,%1,%2,%3};"
        : "+f"(c[0]), "+f"(c[1]), "+f"(c[2]), "+f"(c[3])
        : "r"(a[0]), "r"(a[1]), "r"(a[2]), "r"(a[3]), "r"(b0), "r"(b1));
}

// ---------------- CSR build --------------------------------------------------
__global__ void zero_cursor_kernel() {
    int i = blockIdx.x * blockDim.x + threadIdx.x;
    if (i < NN) g_cursor[i] = 0;
}

__global__ void hist_kernel(const int* __restrict__ ei) {
    int e = blockIdx.x * blockDim.x + threadIdx.x;
    if (e < NE) {
        int dst = ei[NE + e];
        if ((unsigned)dst < NN) atomicAdd(&g_cursor[dst], 1);
    }
}

__global__ void scan1_kernel() {
    const int tid  = threadIdx.x;
    const int lane = tid & 31;
    const int warp = tid >> 5;
    const int i    = blockIdx.x * 1024 + tid;
    int v = (i < NN) ? g_cursor[i] : 0;
    int x = v;
    #pragma unroll
    for (int off = 1; off < 32; off <<= 1) {
        int t = __shfl_up_sync(0xFFFFFFFFu, x, off);
        if (lane >= off) x += t;
    }
    __shared__ int wsum[32];
    if (lane == 31) wsum[warp] = x;
    __syncthreads();
    if (warp == 0) {
        int y = wsum[lane];
        #pragma unroll
        for (int off = 1; off < 32; off <<= 1) {
            int t = __shfl_up_sync(0xFFFFFFFFu, y, off);
            if (lane >= off) y += t;
        }
        wsum[lane] = y;
    }
    __syncthreads();
    int blockExcl = (warp > 0) ? wsum[warp - 1] : 0;
    if (i < NN) g_rowptr[i] = blockExcl + x - v;
    if (tid == 1023) g_blocksum[blockIdx.x] = blockExcl + x;
}

__global__ void scan2_kernel() {   // 1 block, 128 threads
    __shared__ int s[128];
    int tid = threadIdx.x;
    int v = (tid < SCAN_BLOCKS) ? g_blocksum[tid] : 0;
    s[tid] = v;
    __syncthreads();
    #pragma unroll
    for (int off = 1; off < 128; off <<= 1) {
        int t = (tid >= off) ? s[tid - off] : 0;
        __syncthreads();
        s[tid] += t;
        __syncthreads();
    }
    if (tid < SCAN_BLOCKS) g_blocksum[tid] = s[tid] - v;
    if (tid == SCAN_BLOCKS - 1) g_rowptr[NN] = s[tid];
}

__global__ void scan3_kernel() {
    int i = blockIdx.x * 1024 + threadIdx.x;
    if (i < NN) g_rowptr[i] += g_blocksum[blockIdx.x];
}

__global__ void fill_kernel(const int* __restrict__ ei) {
    int e = blockIdx.x * blockDim.x + threadIdx.x;
    if (e < NE) {
        int src = ei[e];
        int dst = ei[NE + e];
        if ((unsigned)dst < NN && (unsigned)src < NN) {
            int pos = atomicAdd(&g_cursor[dst], 1);
            g_col[g_rowptr[dst] + pos] = src;
        }
    }
}

// ---------------- weight prep: WT[l][n][k] = tf32(W[l][k][n]) ----------------
__global__ void prep_wt_kernel(const float* __restrict__ wr1, const float* __restrict__ wo1,
                               const float* __restrict__ wr2, const float* __restrict__ wo2,
                               const float* __restrict__ wr3, const float* __restrict__ wo3) {
    int i = blockIdx.x * blockDim.x + threadIdx.x;   // over 3*128*256
    if (i >= 3 * 128 * 256) return;
    int l = i >> 15;
    int r = i & 32767;
    int n = r >> 8;
    int k = r & 255;
    const float* wr = (l == 0) ? wr1 : (l == 1 ? wr2 : wr3);
    const float* wo = (l == 0) ? wo1 : (l == 1 ? wo2 : wo3);
    float v = (k < 128) ? wr[k * 128 + n] : wo[(k - 128) * 128 + n];
    g_wt[i] = tf32_rna(v);
}

// ---------------- x -> fp16 copy ----------------------------------------------
__global__ void cvt_x_kernel(const float* __restrict__ x) {
    int i = blockIdx.x * blockDim.x + threadIdx.x;   // per float4 (12.8M/4)
    if (i >= NN * D / 4) return;
    float4 v = ((const float4*)x)[i];
    __half2 h0 = __floats2half2_rn(v.x, v.y);
    __half2 h1 = __floats2half2_rn(v.z, v.w);
    uint2 u = make_uint2(*(uint32_t*)&h0, *(uint32_t*)&h1);
    ((uint2*)g_hh)[i] = u;
}

// ---------------- aggregation: one warp per node, fp16 source ----------------
// lane loads uint2 = 4 halfs; accumulates 4 fp32; writes float4 to g_agg.
__global__ void agg_kernel() {
    int gw   = (blockIdx.x * blockDim.x + threadIdx.x) >> 5;
    int lane = threadIdx.x & 31;
    if (gw >= NN) return;
    int beg = g_rowptr[gw];
    int end = g_rowptr[gw + 1];
    const uint2* hv = (const uint2*)g_hh;   // 32 uint2 per row
    float4 acc = make_float4(0.f, 0.f, 0.f, 0.f);
    int j = beg;
    for (; j + 4 <= end; j += 4) {
        int s0 = g_col[j], s1 = g_col[j + 1], s2 = g_col[j + 2], s3 = g_col[j + 3];
        uint2 u0 = hv[(size_t)s0 * 32 + lane];
        uint2 u1 = hv[(size_t)s1 * 32 + lane];
        uint2 u2 = hv[(size_t)s2 * 32 + lane];
        uint2 u3 = hv[(size_t)s3 * 32 + lane];
        float2 a0 = __half22float2(*(__half2*)&u0.x), b0 = __half22float2(*(__half2*)&u0.y);
        float2 a1 = __half22float2(*(__half2*)&u1.x), b1 = __half22float2(*(__half2*)&u1.y);
        float2 a2 = __half22float2(*(__half2*)&u2.x), b2 = __half22float2(*(__half2*)&u2.y);
        float2 a3 = __half22float2(*(__half2*)&u3.x), b3 = __half22float2(*(__half2*)&u3.y);
        acc.x += a0.x + a1.x + a2.x + a3.x;
        acc.y += a0.y + a1.y + a2.y + a3.y;
        acc.z += b0.x + b1.x + b2.x + b3.x;
        acc.w += b0.y + b1.y + b2.y + b3.y;
    }
    for (; j < end; j++) {
        int s = g_col[j];
        uint2 u = hv[(size_t)s * 32 + lane];
        float2 a = __half22float2(*(__half2*)&u.x), b = __half22float2(*(__half2*)&u.y);
        acc.x += a.x; acc.y += a.y; acc.z += b.x; acc.w += b.y;
    }
    *(float4*)&g_agg[(size_t)gw * 128 + lane * 4] = acc;
}

// ---------------- TF32 mma.sync GEMM: out = act([g_agg|h] @ WT^T + b) --------
// 128x128 tile, K=256 in 8 chunks of 32. 256 threads = 8 warps (4 M x 2 N),
// warp tile 32(M) x 64(N) = 2x8 m16n8k8 tiles, 64 fp32 acc/thread.
template <bool RELU>
__global__ void __launch_bounds__(256, 2)
gemm_mma_kernel(const float* __restrict__ xin, int which,
                const float* __restrict__ bias,
                float* __restrict__ outarg, int outsel, int writeH)
{
    __shared__ float sA[4096];
    __shared__ float sB[4096];

    const float* A1  = (which == 0) ? xin : (which == 1 ? g_h1 : g_h2);
    float*       out = (outsel == 0) ? g_h1 : (outsel == 1 ? g_h2 : outarg);
    const float* wt  = &g_wt[which * 128 * 256];   // layer == which

    const int tid  = threadIdx.x;
    const int lane = tid & 31;
    const int wid  = tid >> 5;
    const int wm   = wid & 3;     // 0..3  -> M
    const int wn   = wid >> 2;    // 0..1  -> N
    const int m0   = blockIdx.x * 128;

    float acc[2][8][4];
    #pragma unroll
    for (int i = 0; i < 2; i++)
        #pragma unroll
        for (int j = 0; j < 8; j++)
            #pragma unroll
            for (int k = 0; k < 4; k++) acc[i][j][k] = 0.f;

    #pragma unroll 1
    for (int c = 0; c < 8; c++) {
        __syncthreads();

        // ---- stage A chunk (fragment-major, tf32-converted) ----
        {
            const float* A    = (c < 4) ? g_agg : A1;
            const int    kbase = (c & 3) * 32;
            #pragma unroll
            for (int it = 0; it < 4; it++) {
                int fidx = it * 256 + tid;
                int r  = fidx >> 3;
                int cq = fidx & 7;
                float4 v = make_float4(0.f, 0.f, 0.f, 0.f);
                if (m0 + r < NN)
                    v = *(const float4*)&A[(size_t)(m0 + r) * 128 + kbase + cq * 4];
                int mt = r >> 4, rr = r & 15, g = rr & 7, jo = rr >> 3;
                int ks = cq >> 1;
                int j  = jo + ((cq & 1) << 1);
                int base = (ks * 8 + mt) * 128 + g * 16 + j;
                sA[base +  0] = tf32_rna(v.x);
                sA[base +  4] = tf32_rna(v.y);
                sA[base +  8] = tf32_rna(v.z);
                sA[base + 12] = tf32_rna(v.w);
            }
        }
        // ---- stage B chunk (fragment-major; wt already tf32) ----
        {
            const int kbase = c * 32;
            #pragma unroll
            for (int it = 0; it < 4; it++) {
                int fidx = it * 256 + tid;
                int n  = fidx >> 3;
                int cq = fidx & 7;
                float4 v = *(const float4*)&wt[(size_t)n * 256 + kbase + cq * 4];
                int nt = n >> 3, g = n & 7;
                int ks = cq >> 1;
                int j  = cq & 1;
                int base = (ks * 16 + nt) * 64 + g * 8 + j;
                sB[base + 0] = v.x;
                sB[base + 2] = v.y;
                sB[base + 4] = v.z;
                sB[base + 6] = v.w;
            }
        }
        __syncthreads();

        // ---- compute: 4 ksteps x (2 M-tiles x 8 N-tiles) mma ----
        #pragma unroll
        for (int ks = 0; ks < 4; ks++) {
            uint32_t a[2][4];
            #pragma unroll
            for (int mtl = 0; mtl < 2; mtl++) {
                int mt = wm * 2 + mtl;
                float4 af = *(const float4*)&sA[((ks * 8 + mt) * 32 + lane) * 4];
                a[mtl][0] = __float_as_uint(af.x);
                a[mtl][1] = __float_as_uint(af.y);
                a[mtl][2] = __float_as_uint(af.z);
                a[mtl][3] = __float_as_uint(af.w);
            }
            #pragma unroll
            for (int ntl = 0; ntl < 8; ntl++) {
                int nt = wn * 8 + ntl;
                float2 bf = *(const float2*)&sB[((ks * 16 + nt) * 32 + lane) * 2];
                uint32_t b0 = __float_as_uint(bf.x);
                uint32_t b1 = __float_as_uint(bf.y);
                mma_tf32(acc[0][ntl], a[0], b0, b1);
                mma_tf32(acc[1][ntl], a[1], b0, b1);
            }
        }
    }

    // ---- epilogue: bias + optional relu; fp32 store + optional fp16 copy ----
    const int g   = lane >> 2;
    const int tig = lane & 3;
    #pragma unroll
    for (int mtl = 0; mtl < 2; mtl++) {
        #pragma unroll
        for (int h = 0; h < 2; h++) {
            int row = m0 + wm * 32 + mtl * 16 + h * 8 + g;
            if (row >= NN) continue;
            #pragma unroll
            for (int ntl = 0; ntl < 8; ntl++) {
                int col = wn * 64 + ntl * 8 + tig * 2;
                float2 o;
                o.x = acc[mtl][ntl][h * 2 + 0] + __ldg(&bias[col + 0]);
                o.y = acc[mtl][ntl][h * 2 + 1] + __ldg(&bias[col + 1]);
                if (RELU) { o.x = fmaxf(o.x, 0.f); o.y = fmaxf(o.y, 0.f); }
                *(float2*)&out[(size_t)row * 128 + col] = o;
                if (writeH) {
                    __half2 hh = __floats2half2_rn(o.x, o.y);
                    *(__half2*)&g_hh[(size_t)row * 128 + col] = hh;
                }
            }
        }
    }
}

// ---------------- launch ------------------------------------------------------
extern "C" void kernel_launch(void* const* d_in, const int* in_sizes, int n_in,
                              void* d_out, int out_size) {
    const float* x       = (const float*)d_in[0];
    const int*   ei      = (const int*)d_in[1];
    const float* w_rel1  = (const float*)d_in[2];
    const float* w_root1 = (const float*)d_in[3];
    const float* b1      = (const float*)d_in[4];
    const float* w_rel2  = (const float*)d_in[5];
    const float* w_root2 = (const float*)d_in[6];
    const float* b2      = (const float*)d_in[7];
    const float* w_rel3  = (const float*)d_in[8];
    const float* w_root3 = (const float*)d_in[9];
    const float* b3      = (const float*)d_in[10];
    float*       out     = (float*)d_out;

    const int ZB = (NN + 255) / 256;
    const int EB = (NE + 255) / 256;
    const int AB = ((NN * 32) + 255) / 256;
    const int GB = (NN + 127) / 128;            // 782
    const int CB = (NN * D / 4 + 255) / 256;    // 12500

    // CSR build + weight prep + fp16 x copy
    zero_cursor_kernel<<<ZB, 256>>>();
    hist_kernel<<<EB, 256>>>(ei);
    prep_wt_kernel<<<384, 256>>>(w_rel1, w_root1, w_rel2, w_root2, w_rel3, w_root3);
    cvt_x_kernel<<<CB, 256>>>(x);
    scan1_kernel<<<SCAN_BLOCKS, 1024>>>();
    scan2_kernel<<<1, 128>>>();
    scan3_kernel<<<SCAN_BLOCKS, 1024>>>();
    zero_cursor_kernel<<<ZB, 256>>>();
    fill_kernel<<<EB, 256>>>(ei);

    // layer 1
    agg_kernel<<<AB, 256>>>();
    gemm_mma_kernel<true><<<GB, 256>>>(x, 0, b1, nullptr, 0, 1);
    // layer 2
    agg_kernel<<<AB, 256>>>();
    gemm_mma_kernel<true><<<GB, 256>>>(x, 1, b2, nullptr, 1, 1);
    // layer 3 (no relu) -> d_out
    agg_kernel<<<AB, 256>>>();
    gemm_mma_kernel<false><<<GB, 256>>>(x, 2, b3, out, 2, 0);
}

// round 9
// speedup vs baseline: 2.1575x; 1.4991x over previous
#include <cuda_runtime.h>
#include <cuda_fp16.h>
#include <cstdint>

#define NN 100000
#define NE 1600000
#define D  128
#define SCAN_BLOCKS 98   // ceil(NN / 1024)

// ---------------- scratch (device globals — no allocation allowed) ----------
__device__ __align__(16) int    g_cursor[NN];
__device__ __align__(16) int    g_rowptr[NN + 1];
__device__ __align__(16) int    g_blocksum[SCAN_BLOCKS];
__device__ __align__(16) int    g_col[NE];
__device__ __align__(16) __half g_hh  [(size_t)NN * D];   // fp16 node features (current layer input)
__device__ __align__(16) __half g_aggh[(size_t)NN * D];   // fp16 aggregated features
// pre-transposed fp16 weights: WTH[layer][n=128][k=256] = [w_rel;w_root]^T
__device__ __align__(16) __half g_wth [3 * 128 * 256];

// fp16 tensor-core mma, fp32 accumulate (baseline PTX, works on compute_103)
__device__ __forceinline__ void mma_f16(float* c, const uint32_t* a,
                                        uint32_t b0, uint32_t b1) {
    asm volatile(
        "mma.sync.aligned.m16n8k16.row.col.f32.f16.f16.f32 "
        "{%0,%1,%2,%3}, {%4,%5,%6,%7}, {%8,%9}, {%0,%1,%2,%3};"
        : "+f"(c[0]), "+f"(c[1]), "+f"(c[2]), "+f"(c[3])
        : "r"(a[0]), "r"(a[1]), "r"(a[2]), "r"(a[3]), "r"(b0), "r"(b1));
}

// ---------------- CSR build --------------------------------------------------
__global__ void zero_cursor_kernel() {
    int i = blockIdx.x * blockDim.x + threadIdx.x;
    if (i < NN) g_cursor[i] = 0;
}

__global__ void hist_kernel(const int* __restrict__ ei) {
    int e = blockIdx.x * blockDim.x + threadIdx.x;
    if (e < NE) {
        int dst = ei[NE + e];
        if ((unsigned)dst < NN) atomicAdd(&g_cursor[dst], 1);
    }
}

__global__ void scan1_kernel() {
    const int tid  = threadIdx.x;
    const int lane = tid & 31;
    const int warp = tid >> 5;
    const int i    = blockIdx.x * 1024 + tid;
    int v = (i < NN) ? g_cursor[i] : 0;
    int x = v;
    #pragma unroll
    for (int off = 1; off < 32; off <<= 1) {
        int t = __shfl_up_sync(0xFFFFFFFFu, x, off);
        if (lane >= off) x += t;
    }
    __shared__ int wsum[32];
    if (lane == 31) wsum[warp] = x;
    __syncthreads();
    if (warp == 0) {
        int y = wsum[lane];
        #pragma unroll
        for (int off = 1; off < 32; off <<= 1) {
            int t = __shfl_up_sync(0xFFFFFFFFu, y, off);
            if (lane >= off) y += t;
        }
        wsum[lane] = y;
    }
    __syncthreads();
    int blockExcl = (warp > 0) ? wsum[warp - 1] : 0;
    if (i < NN) g_rowptr[i] = blockExcl + x - v;
    if (tid == 1023) g_blocksum[blockIdx.x] = blockExcl + x;
}

__global__ void scan2_kernel() {   // 1 block, 128 threads
    __shared__ int s[128];
    int tid = threadIdx.x;
    int v = (tid < SCAN_BLOCKS) ? g_blocksum[tid] : 0;
    s[tid] = v;
    __syncthreads();
    #pragma unroll
    for (int off = 1; off < 128; off <<= 1) {
        int t = (tid >= off) ? s[tid - off] : 0;
        __syncthreads();
        s[tid] += t;
        __syncthreads();
    }
    if (tid < SCAN_BLOCKS) g_blocksum[tid] = s[tid] - v;
    if (tid == SCAN_BLOCKS - 1) g_rowptr[NN] = s[tid];
}

__global__ void scan3_kernel() {
    int i = blockIdx.x * 1024 + threadIdx.x;
    if (i < NN) g_rowptr[i] += g_blocksum[blockIdx.x];
}

__global__ void fill_kernel(const int* __restrict__ ei) {
    int e = blockIdx.x * blockDim.x + threadIdx.x;
    if (e < NE) {
        int src = ei[e];
        int dst = ei[NE + e];
        if ((unsigned)dst < NN && (unsigned)src < NN) {
            int pos = atomicAdd(&g_cursor[dst], 1);
            g_col[g_rowptr[dst] + pos] = src;
        }
    }
}

// ---------------- weight prep: WTH[l][n][k] = fp16(W[l][k][n]) ---------------
__global__ void prep_wt_kernel(const float* __restrict__ wr1, const float* __restrict__ wo1,
                               const float* __restrict__ wr2, const float* __restrict__ wo2,
                               const float* __restrict__ wr3, const float* __restrict__ wo3) {
    int i = blockIdx.x * blockDim.x + threadIdx.x;   // over 3*128*256
    if (i >= 3 * 128 * 256) return;
    int l = i >> 15;
    int r = i & 32767;
    int n = r >> 8;
    int k = r & 255;
    const float* wr = (l == 0) ? wr1 : (l == 1 ? wr2 : wr3);
    const float* wo = (l == 0) ? wo1 : (l == 1 ? wo2 : wo3);
    float v = (k < 128) ? wr[k * 128 + n] : wo[(k - 128) * 128 + n];
    g_wth[i] = __float2half_rn(v);
}

// ---------------- x -> fp16 copy ----------------------------------------------
__global__ void cvt_x_kernel(const float* __restrict__ x) {
    int i = blockIdx.x * blockDim.x + threadIdx.x;   // per float4
    if (i >= NN * D / 4) return;
    float4 v = ((const float4*)x)[i];
    __half2 h0 = __floats2half2_rn(v.x, v.y);
    __half2 h1 = __floats2half2_rn(v.z, v.w);
    ((uint2*)g_hh)[i] = make_uint2(*(uint32_t*)&h0, *(uint32_t*)&h1);
}

// ---------------- aggregation: one warp per node, fp16 in/out ----------------
__global__ void agg_kernel() {
    int gw   = (blockIdx.x * blockDim.x + threadIdx.x) >> 5;
    int lane = threadIdx.x & 31;
    if (gw >= NN) return;
    int beg = g_rowptr[gw];
    int end = g_rowptr[gw + 1];
    const uint2* hv = (const uint2*)g_hh;   // 32 uint2 per row
    float4 acc = make_float4(0.f, 0.f, 0.f, 0.f);
    int j = beg;
    for (; j + 4 <= end; j += 4) {
        int s0 = g_col[j], s1 = g_col[j + 1], s2 = g_col[j + 2], s3 = g_col[j + 3];
        uint2 u0 = hv[(size_t)s0 * 32 + lane];
        uint2 u1 = hv[(size_t)s1 * 32 + lane];
        uint2 u2 = hv[(size_t)s2 * 32 + lane];
        uint2 u3 = hv[(size_t)s3 * 32 + lane];
        float2 a0 = __half22float2(*(__half2*)&u0.x), b0 = __half22float2(*(__half2*)&u0.y);
        float2 a1 = __half22float2(*(__half2*)&u1.x), b1 = __half22float2(*(__half2*)&u1.y);
        float2 a2 = __half22float2(*(__half2*)&u2.x), b2 = __half22float2(*(__half2*)&u2.y);
        float2 a3 = __half22float2(*(__half2*)&u3.x), b3 = __half22float2(*(__half2*)&u3.y);
        acc.x += a0.x + a1.x + a2.x + a3.x;
        acc.y += a0.y + a1.y + a2.y + a3.y;
        acc.z += b0.x + b1.x + b2.x + b3.x;
        acc.w += b0.y + b1.y + b2.y + b3.y;
    }
    for (; j < end; j++) {
        int s = g_col[j];
        uint2 u = hv[(size_t)s * 32 + lane];
        float2 a = __half22float2(*(__half2*)&u.x), b = __half22float2(*(__half2*)&u.y);
        acc.x += a.x; acc.y += a.y; acc.z += b.x; acc.w += b.y;
    }
    __half2 h0 = __floats2half2_rn(acc.x, acc.y);
    __half2 h1 = __floats2half2_rn(acc.z, acc.w);
    ((uint2*)g_aggh)[(size_t)gw * 32 + lane] = make_uint2(*(uint32_t*)&h0, *(uint32_t*)&h1);
}

// ---------------- fp16 mma.sync GEMM: out = act([g_aggh | g_hh] @ WTH^T + b) -
// 128x128 tile, K=256 in 8 chunks of 32 (2 ksteps of 16 each).
// 256 threads = 8 warps (4M x 2N), warp tile 32x64 = 2x8 m16n8k16, 64 acc/thread.
// Fragment-major staged SMEM: sA 2048 u32 (8KB), sB 2048 u32 (8KB).
// LAST=false: relu + fp16 store to g_hh.  LAST=true: no relu + fp32 store to out.
template <bool LAST>
__global__ void __launch_bounds__(256, 2)
gemm_mma_kernel(int layer, const float* __restrict__ bias, float* __restrict__ out)
{
    __shared__ uint32_t sA[2048];
    __shared__ uint32_t sB[2048];

    const __half* wth = &g_wth[layer * 128 * 256];

    const int tid  = threadIdx.x;
    const int lane = tid & 31;
    const int wid  = tid >> 5;
    const int wm   = wid & 3;     // 0..3  -> M
    const int wn   = wid >> 2;    // 0..1  -> N
    const int m0   = blockIdx.x * 128;

    float acc[2][8][4];
    #pragma unroll
    for (int i = 0; i < 2; i++)
        #pragma unroll
        for (int j = 0; j < 8; j++)
            #pragma unroll
            for (int k = 0; k < 4; k++) acc[i][j][k] = 0.f;

    #pragma unroll 1
    for (int c = 0; c < 8; c++) {
        __syncthreads();

        // ---- stage A chunk: rows m0..m0+127, 32 halfs starting at (c&3)*32 ----
        {
            const __half* Asrc = (c < 4) ? g_aggh : g_hh;
            const int kb_u2 = (c & 3) * 8;   // uint2 (4-half) offset within row
            #pragma unroll
            for (int it = 0; it < 4; it++) {
                int fidx = it * 256 + tid;    // 1024 uint2 units
                int r = fidx >> 3, q = fidx & 7;
                uint2 u = make_uint2(0u, 0u);
                if (m0 + r < NN)
                    u = ((const uint2*)Asrc)[(size_t)(m0 + r) * 32 + kb_u2 + q];
                int mt = r >> 4, jo = (r >> 3) & 1, g = r & 7;
                #pragma unroll
                for (int j = 0; j < 2; j++) {
                    int cc2 = q * 2 + j;              // b32 (half2) index 0..15
                    int ks  = cc2 >> 3;
                    int c2  = cc2 & 7;
                    int tig = c2 & 3;
                    int reg = (c2 >> 2) * 2 + jo;     // a0..a3
                    sA[((ks * 8 + mt) * 32 + g * 4 + tig) * 4 + reg] = j ? u.y : u.x;
                }
            }
        }
        // ---- stage B chunk: WTH n=0..127, 32 halfs starting at c*32 ----
        {
            const int kbq = c * 8;
            #pragma unroll
            for (int it = 0; it < 4; it++) {
                int fidx = it * 256 + tid;
                int n = fidx >> 3, q = fidx & 7;
                uint2 u = ((const uint2*)wth)[(size_t)n * 64 + kbq + q];
                int nt = n >> 3, gg = n & 7;
                #pragma unroll
                for (int j = 0; j < 2; j++) {
                    int cc2 = q * 2 + j;
                    int ks  = cc2 >> 3;
                    int c2  = cc2 & 7;
                    int tig = c2 & 3;
                    int reg = c2 >> 2;                // b0 / b1
                    sB[((ks * 16 + nt) * 32 + gg * 4 + tig) * 2 + reg] = j ? u.y : u.x;
                }
            }
        }
        __syncthreads();

        // ---- compute: 2 ksteps x (2 M-tiles x 8 N-tiles) m16n8k16 ----
        #pragma unroll
        for (int ks = 0; ks < 2; ks++) {
            uint32_t a[2][4];
            #pragma unroll
            for (int mtl = 0; mtl < 2; mtl++) {
                int mt = wm * 2 + mtl;
                uint4 av = *(const uint4*)&sA[((ks * 8 + mt) * 32 + lane) * 4];
                a[mtl][0] = av.x; a[mtl][1] = av.y; a[mtl][2] = av.z; a[mtl][3] = av.w;
            }
            #pragma unroll
            for (int ntl = 0; ntl < 8; ntl++) {
                int nt = wn * 8 + ntl;
                uint2 bv = *(const uint2*)&sB[((ks * 16 + nt) * 32 + lane) * 2];
                mma_f16(acc[0][ntl], a[0], bv.x, bv.y);
                mma_f16(acc[1][ntl], a[1], bv.x, bv.y);
            }
        }
    }

    // ---- epilogue ----
    const int g   = lane >> 2;
    const int tig = lane & 3;
    #pragma unroll
    for (int mtl = 0; mtl < 2; mtl++) {
        #pragma unroll
        for (int h = 0; h < 2; h++) {
            int row = m0 + wm * 32 + mtl * 16 + h * 8 + g;
            if (row >= NN) continue;
            #pragma unroll
            for (int ntl = 0; ntl < 8; ntl++) {
                int col = wn * 64 + ntl * 8 + tig * 2;
                float ox = acc[mtl][ntl][h * 2 + 0] + __ldg(&bias[col + 0]);
                float oy = acc[mtl][ntl][h * 2 + 1] + __ldg(&bias[col + 1]);
                if (!LAST) {
                    ox = fmaxf(ox, 0.f); oy = fmaxf(oy, 0.f);
                    __half2 hh = __floats2half2_rn(ox, oy);
                    *(__half2*)&g_hh[(size_t)row * 128 + col] = hh;
                } else {
                    *(float2*)&out[(size_t)row * 128 + col] = make_float2(ox, oy);
                }
            }
        }
    }
}

// ---------------- launch ------------------------------------------------------
extern "C" void kernel_launch(void* const* d_in, const int* in_sizes, int n_in,
                              void* d_out, int out_size) {
    const float* x       = (const float*)d_in[0];
    const int*   ei      = (const int*)d_in[1];
    const float* w_rel1  = (const float*)d_in[2];
    const float* w_root1 = (const float*)d_in[3];
    const float* b1      = (const float*)d_in[4];
    const float* w_rel2  = (const float*)d_in[5];
    const float* w_root2 = (const float*)d_in[6];
    const float* b2      = (const float*)d_in[7];
    const float* w_rel3  = (const float*)d_in[8];
    const float* w_root3 = (const float*)d_in[9];
    const float* b3      = (const float*)d_in[10];
    float*       out     = (float*)d_out;

    const int ZB = (NN + 255) / 256;
    const int EB = (NE + 255) / 256;
    const int AB = ((NN * 32) + 255) / 256;
    const int GB = (NN + 127) / 128;            // 782
    const int CB = (NN * D / 4 + 255) / 256;    // 12500

    // CSR build + weight prep + fp16 x copy
    zero_cursor_kernel<<<ZB, 256>>>();
    hist_kernel<<<EB, 256>>>(ei);
    prep_wt_kernel<<<384, 256>>>(w_rel1, w_root1, w_rel2, w_root2, w_rel3, w_root3);
    cvt_x_kernel<<<CB, 256>>>(x);
    scan1_kernel<<<SCAN_BLOCKS, 1024>>>();
    scan2_kernel<<<1, 128>>>();
    scan3_kernel<<<SCAN_BLOCKS, 1024>>>();
    zero_cursor_kernel<<<ZB, 256>>>();
    fill_kernel<<<EB, 256>>>(ei);

    // layer 1
    agg_kernel<<<AB, 256>>>();
    gemm_mma_kernel<false><<<GB, 256>>>(0, b1, nullptr);
    // layer 2
    agg_kernel<<<AB, 256>>>();
    gemm_mma_kernel<false><<<GB, 256>>>(1, b2, nullptr);
    // layer 3 (no relu) -> d_out
    agg_kernel<<<AB, 256>>>();
    gemm_mma_kernel<true><<<GB, 256>>>(2, b3, out);
}

// round 10
// speedup vs baseline: 2.3676x; 1.0974x over previous
#include <cuda_runtime.h>
#include <cuda_fp16.h>
#include <cstdint>

#define NN 100000
#define NE 1600000
#define D  128
#define SCAN_BLOCKS 98   // ceil(NN / 1024)

// ---------------- scratch (device globals — no allocation allowed) ----------
__device__ __align__(16) int    g_cursor[NN];
__device__ __align__(16) int    g_rowptr[NN + 1];
__device__ __align__(16) int    g_blocksum[SCAN_BLOCKS];
__device__ __align__(16) int    g_col[NE];
__device__ __align__(16) __half g_hh  [(size_t)NN * D];   // fp16 node features (layer input)
__device__ __align__(16) __half g_aggh[(size_t)NN * D];   // fp16 aggregated features
// fragment-major fp16 weights: per layer 16 ksteps x 16 ntiles x 32 lanes x uint2
__device__ __align__(16) uint2  g_wtf [3 * 8192];

// fp16 tensor-core mma, fp32 accumulate (baseline PTX, works on compute_103)
__device__ __forceinline__ void mma_f16(float* c, const uint32_t* a,
                                        uint32_t b0, uint32_t b1) {
    asm volatile(
        "mma.sync.aligned.m16n8k16.row.col.f32.f16.f16.f32 "
        "{%0,%1,%2,%3}, {%4,%5,%6,%7}, {%8,%9}, {%0,%1,%2,%3};"
        : "+f"(c[0]), "+f"(c[1]), "+f"(c[2]), "+f"(c[3])
        : "r"(a[0]), "r"(a[1]), "r"(a[2]), "r"(a[3]), "r"(b0), "r"(b1));
}

__device__ __forceinline__ void ldmatrix_x4(uint32_t* a, uint32_t addr) {
    asm volatile("ldmatrix.sync.aligned.m8n8.x4.shared.b16 {%0,%1,%2,%3}, [%4];"
                 : "=r"(a[0]), "=r"(a[1]), "=r"(a[2]), "=r"(a[3]) : "r"(addr));
}

__device__ __forceinline__ void cp_async16(uint32_t dst, const void* src, int szbytes) {
    asm volatile("cp.async.cg.shared.global [%0], [%1], 16, %2;"
                 :: "r"(dst), "l"(src), "r"(szbytes) : "memory");
}
__device__ __forceinline__ uint32_t smem_u32(const void* p) {
    uint32_t a;
    asm("{ .reg .u64 t; cvta.to.shared.u64 t, %1; cvt.u32.u64 %0, t; }" : "=r"(a) : "l"(p));
    return a;
}

// ---------------- CSR build --------------------------------------------------
__global__ void zero_cursor_kernel() {
    int i = blockIdx.x * blockDim.x + threadIdx.x;
    if (i < NN) g_cursor[i] = 0;
}

__global__ void hist_kernel(const int* __restrict__ ei) {
    int e = blockIdx.x * blockDim.x + threadIdx.x;
    if (e < NE) {
        int dst = ei[NE + e];
        if ((unsigned)dst < NN) atomicAdd(&g_cursor[dst], 1);
    }
}

__global__ void scan1_kernel() {
    const int tid  = threadIdx.x;
    const int lane = tid & 31;
    const int warp = tid >> 5;
    const int i    = blockIdx.x * 1024 + tid;
    int v = (i < NN) ? g_cursor[i] : 0;
    int x = v;
    #pragma unroll
    for (int off = 1; off < 32; off <<= 1) {
        int t = __shfl_up_sync(0xFFFFFFFFu, x, off);
        if (lane >= off) x += t;
    }
    __shared__ int wsum[32];
    if (lane == 31) wsum[warp] = x;
    __syncthreads();
    if (warp == 0) {
        int y = wsum[lane];
        #pragma unroll
        for (int off = 1; off < 32; off <<= 1) {
            int t = __shfl_up_sync(0xFFFFFFFFu, y, off);
            if (lane >= off) y += t;
        }
        wsum[lane] = y;
    }
    __syncthreads();
    int blockExcl = (warp > 0) ? wsum[warp - 1] : 0;
    if (i < NN) g_rowptr[i] = blockExcl + x - v;
    if (tid == 1023) g_blocksum[blockIdx.x] = blockExcl + x;
}

__global__ void scan2_kernel() {   // 1 block, 128 threads
    __shared__ int s[128];
    int tid = threadIdx.x;
    int v = (tid < SCAN_BLOCKS) ? g_blocksum[tid] : 0;
    s[tid] = v;
    __syncthreads();
    #pragma unroll
    for (int off = 1; off < 128; off <<= 1) {
        int t = (tid >= off) ? s[tid - off] : 0;
        __syncthreads();
        s[tid] += t;
        __syncthreads();
    }
    if (tid < SCAN_BLOCKS) g_blocksum[tid] = s[tid] - v;
    if (tid == SCAN_BLOCKS - 1) g_rowptr[NN] = s[tid];
}

// adds block offsets AND initializes fill cursor to absolute row starts
__global__ void scan3_kernel() {
    int i = blockIdx.x * 1024 + threadIdx.x;
    if (i < NN) {
        int v = g_rowptr[i] + g_blocksum[blockIdx.x];
        g_rowptr[i] = v;
        g_cursor[i] = v;
    }
}

__global__ void fill_kernel(const int* __restrict__ ei) {
    int e = blockIdx.x * blockDim.x + threadIdx.x;
    if (e < NE) {
        int src = ei[e];
        int dst = ei[NE + e];
        if ((unsigned)dst < NN && (unsigned)src < NN) {
            int pos = atomicAdd(&g_cursor[dst], 1);
            g_col[pos] = src;
        }
    }
}

// ---------------- weight prep: fragment-major fp16 ---------------------------
// g_wtf[layer][ksg 0..15][nt 0..15][lane 0..31] = uint2 {b0,b1} where
// b_j = half2( W[k][n], W[k+1][n] ), n = nt*8 + lane/4, k = ksg*16 + (lane%4)*2 + j*8,
// W = [w_rel ; w_root] (256 x 128).
__global__ void prep_wt_kernel(const float* __restrict__ wr1, const float* __restrict__ wo1,
                               const float* __restrict__ wr2, const float* __restrict__ wo2,
                               const float* __restrict__ wr3, const float* __restrict__ wo3) {
    int i = blockIdx.x * blockDim.x + threadIdx.x;   // over 49152 half2 slots
    if (i >= 3 * 16384) return;
    int j    = i & 1;
    int lane = (i >> 1) & 31;
    int nt   = (i >> 6) & 15;
    int ksg  = (i >> 10) & 15;
    int l    = i >> 14;
    int n = nt * 8 + (lane >> 2);
    int k = ksg * 16 + (lane & 3) * 2 + j * 8;
    const float* wr = (l == 0) ? wr1 : (l == 1 ? wr2 : wr3);
    const float* wo = (l == 0) ? wo1 : (l == 1 ? wo2 : wo3);
    float v0, v1;
    if (k < 128) { v0 = wr[k * 128 + n];        v1 = wr[(k + 1) * 128 + n]; }
    else         { v0 = wo[(k - 128) * 128 + n]; v1 = wo[(k - 127) * 128 + n]; }
    __half2 h = __floats2half2_rn(v0, v1);
    ((uint32_t*)g_wtf)[i] = *(uint32_t*)&h;
}

// ---------------- x -> fp16 copy ----------------------------------------------
__global__ void cvt_x_kernel(const float* __restrict__ x) {
    int i = blockIdx.x * blockDim.x + threadIdx.x;   // per float4
    if (i >= NN * D / 4) return;
    float4 v = ((const float4*)x)[i];
    __half2 h0 = __floats2half2_rn(v.x, v.y);
    __half2 h1 = __floats2half2_rn(v.z, v.w);
    ((uint2*)g_hh)[i] = make_uint2(*(uint32_t*)&h0, *(uint32_t*)&h1);
}

// ---------------- aggregation: warp/node, 8-edge batches, shfl col bcast -----
__global__ void agg_kernel() {
    int gw   = (blockIdx.x * blockDim.x + threadIdx.x) >> 5;
    int lane = threadIdx.x & 31;
    if (gw >= NN) return;
    int beg = g_rowptr[gw];
    int end = g_rowptr[gw + 1];
    const uint2* hv = (const uint2*)g_hh;   // 32 uint2 per row
    float4 acc = make_float4(0.f, 0.f, 0.f, 0.f);
    int j = beg;
    for (; j + 8 <= end; j += 8) {
        int myc = g_col[j + (lane & 7)];
        int s[8];
        #pragma unroll
        for (int e = 0; e < 8; e++) s[e] = __shfl_sync(0xFFFFFFFFu, myc, e);
        uint2 u[8];
        #pragma unroll
        for (int e = 0; e < 8; e++) u[e] = hv[(size_t)s[e] * 32 + lane];
        #pragma unroll
        for (int e = 0; e < 8; e++) {
            float2 a = __half22float2(*(__half2*)&u[e].x);
            float2 b = __half22float2(*(__half2*)&u[e].y);
            acc.x += a.x; acc.y += a.y; acc.z += b.x; acc.w += b.y;
        }
    }
    if (j < end) {
        int rem = end - j;
        int myc = ((lane & 7) < rem) ? g_col[j + (lane & 7)] : 0;
        for (int e = 0; e < rem; e++) {
            int s = __shfl_sync(0xFFFFFFFFu, myc, e);
            uint2 u = hv[(size_t)s * 32 + lane];
            float2 a = __half22float2(*(__half2*)&u.x);
            float2 b = __half22float2(*(__half2*)&u.y);
            acc.x += a.x; acc.y += a.y; acc.z += b.x; acc.w += b.y;
        }
    }
    __half2 h0 = __floats2half2_rn(acc.x, acc.y);
    __half2 h1 = __floats2half2_rn(acc.z, acc.w);
    ((uint2*)g_aggh)[(size_t)gw * 32 + lane] = make_uint2(*(uint32_t*)&h0, *(uint32_t*)&h1);
}

// ---------------- fp16 GEMM v2: cp.async + ldmatrix + fragment-major B -------
// out = act([g_aggh | g_hh] @ W + b). 128x128 tile, K=256 as 4 chunks of 64,
// double-buffered. 8 warps (4M x 2N), warp tile 32x64 = 2x8 m16n8k16.
// SMEM A buffer: 128 rows x 128B (64 halfs), XOR-swizzled 16B units.
template <bool LAST>
__global__ void __launch_bounds__(256, 2)
gemm_mma_kernel(int layer, const float* __restrict__ bias, float* __restrict__ out)
{
    __shared__ __align__(16) uint8_t sA[2][128 * 128];

    const int tid  = threadIdx.x;
    const int lane = tid & 31;
    const int wid  = tid >> 5;
    const int wm   = wid & 3;     // 0..3  -> M
    const int wn   = wid >> 2;    // 0..1  -> N
    const int m0   = blockIdx.x * 128;
    const uint2* wtf = g_wtf + layer * 8192;
    const uint32_t sbase = smem_u32(sA);

    float acc[2][8][4];
    #pragma unroll
    for (int i = 0; i < 2; i++)
        #pragma unroll
        for (int j = 0; j < 8; j++)
            #pragma unroll
            for (int k = 0; k < 4; k++) acc[i][j][k] = 0.f;

    // stage chunk c into buffer (c&1) via cp.async (16B units, swizzled)
    auto stage = [&](int c) {
        const __half* Asrc = (c < 2) ? g_aggh : g_hh;
        const uint8_t* base = (const uint8_t*)Asrc;
        const int cc = (c & 1) * 128;            // byte offset of chunk within row
        const uint32_t bufb = sbase + (uint32_t)(c & 1) * (128 * 128);
        #pragma unroll
        for (int it = 0; it < 4; it++) {
            int idx = it * 256 + tid;            // 1024 units of 16B
            int r = idx >> 3, u = idx & 7;
            uint32_t dst = bufb + r * 128 + ((u ^ (r & 7)) * 16);
            const uint8_t* src = base + (size_t)(m0 + r) * 256 + cc + u * 16;
            int sz = (m0 + r < NN) ? 16 : 0;
            cp_async16(dst, src, sz);
        }
        asm volatile("cp.async.commit_group;" ::: "memory");
    };

    stage(0);

    #pragma unroll 1
    for (int c = 0; c < 4; c++) {
        if (c < 3) {
            stage(c + 1);
            asm volatile("cp.async.wait_group 1;" ::: "memory");
        } else {
            asm volatile("cp.async.wait_group 0;" ::: "memory");
        }
        __syncthreads();

        const uint32_t bufb = sbase + (uint32_t)(c & 1) * (128 * 128);
        #pragma unroll
        for (int ks = 0; ks < 4; ks++) {
            uint32_t a[2][4];
            #pragma unroll
            for (int mtl = 0; mtl < 2; mtl++) {
                int mt   = wm * 2 + mtl;
                int row  = mt * 16 + (lane & 15);
                int unit = 2 * ks + (lane >> 4);
                uint32_t addr = bufb + row * 128 + ((unit ^ (row & 7)) * 16);
                ldmatrix_x4(a[mtl], addr);
            }
            #pragma unroll
            for (int ntl = 0; ntl < 8; ntl++) {
                uint2 bv = wtf[(((c * 4 + ks) * 16) + wn * 8 + ntl) * 32 + lane];
                mma_f16(acc[0][ntl], a[0], bv.x, bv.y);
                mma_f16(acc[1][ntl], a[1], bv.x, bv.y);
            }
        }
        __syncthreads();   // compute done before next stage overwrites
    }

    // ---- epilogue ----
    const int g   = lane >> 2;
    const int tig = lane & 3;
    #pragma unroll
    for (int mtl = 0; mtl < 2; mtl++) {
        #pragma unroll
        for (int h = 0; h < 2; h++) {
            int row = m0 + wm * 32 + mtl * 16 + h * 8 + g;
            if (row >= NN) continue;
            #pragma unroll
            for (int ntl = 0; ntl < 8; ntl++) {
                int col = wn * 64 + ntl * 8 + tig * 2;
                float ox = acc[mtl][ntl][h * 2 + 0] + __ldg(&bias[col + 0]);
                float oy = acc[mtl][ntl][h * 2 + 1] + __ldg(&bias[col + 1]);
                if (!LAST) {
                    ox = fmaxf(ox, 0.f); oy = fmaxf(oy, 0.f);
                    __half2 hh = __floats2half2_rn(ox, oy);
                    *(__half2*)&g_hh[(size_t)row * 128 + col] = hh;
                } else {
                    *(float2*)&out[(size_t)row * 128 + col] = make_float2(ox, oy);
                }
            }
        }
    }
}

// ---------------- launch ------------------------------------------------------
extern "C" void kernel_launch(void* const* d_in, const int* in_sizes, int n_in,
                              void* d_out, int out_size) {
    const float* x       = (const float*)d_in[0];
    const int*   ei      = (const int*)d_in[1];
    const float* w_rel1  = (const float*)d_in[2];
    const float* w_root1 = (const float*)d_in[3];
    const float* b1      = (const float*)d_in[4];
    const float* w_rel2  = (const float*)d_in[5];
    const float* w_root2 = (const float*)d_in[6];
    const float* b2      = (const float*)d_in[7];
    const float* w_rel3  = (const float*)d_in[8];
    const float* w_root3 = (const float*)d_in[9];
    const float* b3      = (const float*)d_in[10];
    float*       out     = (float*)d_out;

    const int ZB = (NN + 255) / 256;
    const int EB = (NE + 255) / 256;
    const int AB = ((NN * 32) + 255) / 256;
    const int GB = (NN + 127) / 128;            // 782
    const int CB = (NN * D / 4 + 255) / 256;    // 12500

    // CSR build + weight prep + fp16 x copy
    zero_cursor_kernel<<<ZB, 256>>>();
    hist_kernel<<<EB, 256>>>(ei);
    prep_wt_kernel<<<192, 256>>>(w_rel1, w_root1, w_rel2, w_root2, w_rel3, w_root3);
    cvt_x_kernel<<<CB, 256>>>(x);
    scan1_kernel<<<SCAN_BLOCKS, 1024>>>();
    scan2_kernel<<<1, 128>>>();
    scan3_kernel<<<SCAN_BLOCKS, 1024>>>();
    fill_kernel<<<EB, 256>>>(ei);

    // layer 1
    agg_kernel<<<AB, 256>>>();
    gemm_mma_kernel<false><<<GB, 256>>>(0, b1, nullptr);
    // layer 2
    agg_kernel<<<AB, 256>>>();
    gemm_mma_kernel<false><<<GB, 256>>>(1, b2, nullptr);
    // layer 3 (no relu) -> d_out
    agg_kernel<<<AB, 256>>>();
    gemm_mma_kernel<true><<<GB, 256>>>(2, b3, out);
}